// round 5
// baseline (speedup 1.0000x reference)
#include <cuda_runtime.h>
#include <cuda_bf16.h>
#include <stdint.h>

// ---------------------------------------------------------------------------
// Hodge1LapEdgeEncoder
//
// Output (float32): [0,P) idx rows | [P,2P) idx cols | [2P,2P+P*D) dense vals
//   dense[g,ru,rv,:] = padding + sum_{e -> (g,ru,rv)} (edge_attr[e] + pestat[e,0]*fc_w)
//   u = edge_index[0,e] = g*n+ru  (== dense row id), rv = edge_index[1,e] % n
//   Edges of graph g occupy the contiguous range [g*epg, (g+1)*epg).
// ---------------------------------------------------------------------------

#define TB 256
#define CHUNK 2048   // per-pass edge scan window (smem list capacity)

// ===========================================================================
// Tier 1: fully fused single-pass kernel (pow2 n & D4, smem fits).
// Blocks [0, R): one row each. Blocks [R, R+idxBlocks): idx pattern.
// ===========================================================================
__global__ void k_fused(float* __restrict__ out,
                        const int*    __restrict__ ei,      // [2, E]
                        const float*  __restrict__ pestat,  // [E, K]
                        const float4* __restrict__ ea4,     // [E, D4]
                        const float4* __restrict__ w4,      // [D4]
                        const float4* __restrict__ pad4,    // [D4]
                        int E, int K, int s4, int sn,
                        int epg, long long P, int R)
{
    extern __shared__ float smem[];
    const int tid = threadIdx.x;

    if ((int)blockIdx.x >= R) {
        // ---- idx pattern (float4-vectorized; requires n % 4 == 0) ----
        long long P4 = P >> 2;
        long long t = (long long)((int)blockIdx.x - R) * TB + tid;
        if (t >= P4) return;
        long long q = t << 2;
        int nm1  = (1 << sn) - 1;
        long long nnm1 = ((long long)1 << (2 * sn)) - 1;
        int b   = (int)(q >> (2 * sn));
        int rem = (int)(q & nnm1);
        int i   = rem >> sn;
        int j   = rem & nm1;
        float rv = (float)((b << sn) + i);
        float cv = (float)((b << sn) + j);
        ((float4*)out)[t]       = make_float4(rv, rv, rv, rv);
        ((float4*)(out + P))[t] = make_float4(cv, cv + 1.f, cv + 2.f, cv + 3.f);
        return;
    }

    // ---- dense row r ----
    const int r   = blockIdx.x;            // row id == u value
    const int g   = r >> sn;
    const int D4  = 1 << s4;
    const int nD4 = 1 << (sn + s4);        // float4s per row
    const int nm1 = (1 << sn) - 1;

    float4* acc4 = (float4*)smem;
    int*    list = (int*)(acc4 + nD4);
    int*    cnt  = list + CHUNK;

    // Phase A: init accumulator with padding row.
    for (int s = tid; s < nD4; s += TB)
        acc4[s] = __ldg(&pad4[s & (D4 - 1)]);

    // Phase B/C: chunked scan of this graph's edges, accumulate matches.
    const int gbeg = g * epg;
    const int gend = gbeg + epg;
    for (int base = gbeg; base < gend; base += CHUNK) {
        const int lim = (base + CHUNK < gend) ? base + CHUNK : gend;
        if (tid == 0) *cnt = 0;
        __syncthreads();
        for (int i = base + tid; i < lim; i += TB)
            if (__ldg(&ei[i]) == r)
                list[atomicAdd(cnt, 1)] = i;
        __syncthreads();

        const int m = *cnt;
        for (int w = tid; w < (m << s4); w += TB) {
            int li = w >> s4;
            int c  = w & (D4 - 1);
            int e  = list[li];
            int rv = __ldg(&ei[E + e]) & nm1;
            float  p = __ldg(&pestat[(long long)e * K]);
            float4 a = __ldg(&ea4[((long long)e << s4) + c]);
            float4 wv = __ldg(&w4[c]);
            float* dst = smem + (((rv << s4) + c) << 2);   // rv*D + c*4
            atomicAdd(dst + 0, a.x + p * wv.x);
            atomicAdd(dst + 1, a.y + p * wv.y);
            atomicAdd(dst + 2, a.z + p * wv.z);
            atomicAdd(dst + 3, a.w + p * wv.w);
        }
        __syncthreads();
    }

    // Phase D: stream the finished row to the output.
    float4* orow = ((float4*)(out + 2 * P)) + (long long)r * nD4;
    for (int s = tid; s < nD4; s += TB)
        orow[s] = acc4[s];
}

// ===========================================================================
// Tier 2: R4 pow2 two-kernel path (init + global vector atomics).
// ===========================================================================
__device__ __forceinline__ void red_add_v4(float* dst, float4 r)
{
#if __CUDA_ARCH__ >= 900
    asm volatile("red.global.add.v4.f32 [%0], {%1, %2, %3, %4};"
                 :: "l"(dst), "f"(r.x), "f"(r.y), "f"(r.z), "f"(r.w)
                 : "memory");
#else
    atomicAdd(dst + 0, r.x); atomicAdd(dst + 1, r.y);
    atomicAdd(dst + 2, r.z); atomicAdd(dst + 3, r.w);
#endif
}

__global__ void k_init_p2(float* __restrict__ out, const float4* __restrict__ pad4,
                          int sn, long long P, int D4, int idxBlocks)
{
    if ((int)blockIdx.x < idxBlocks) {
        long long P4 = P >> 2;
        long long t = (long long)blockIdx.x * blockDim.x + threadIdx.x;
        if (t >= P4) return;
        long long q = t << 2;
        int nm1  = (1 << sn) - 1;
        long long nnm1 = ((long long)1 << (2 * sn)) - 1;
        int b   = (int)(q >> (2 * sn));
        int rem = (int)(q & nnm1);
        int i   = rem >> sn;
        int j   = rem & nm1;
        float rv = (float)((b << sn) + i);
        float cv = (float)((b << sn) + j);
        ((float4*)out)[t]       = make_float4(rv, rv, rv, rv);
        ((float4*)(out + P))[t] = make_float4(cv, cv + 1.f, cv + 2.f, cv + 3.f);
    } else {
        long long v = (long long)((int)blockIdx.x - idxBlocks) * blockDim.x
                      + threadIdx.x;
        long long V4 = P * (long long)D4;
        if (v >= V4) return;
        int c = (int)threadIdx.x & (D4 - 1);
        ((float4*)(out + 2 * P))[v] = __ldg(&pad4[c]);
    }
}

__global__ void k_scatter_p2(const int* __restrict__ ei, const float* __restrict__ pestat,
                             const float4* __restrict__ ea4, const float4* __restrict__ w4,
                             float* __restrict__ val, int E, int K, int s4, int sn)
{
    int tot = E << s4;
    int t = blockIdx.x * blockDim.x + threadIdx.x;
    if (t >= tot) return;
    int e = t >> s4;
    int c = t & ((1 << s4) - 1);
    int nm1 = (1 << sn) - 1;

    int u = __ldg(&ei[e]);
    int v = __ldg(&ei[E + e]);
    int rv = v & nm1;

    float  p = __ldg(&pestat[(long long)e * K]);
    float4 a = __ldg(&ea4[((long long)e << s4) + c]);
    float4 w = __ldg(&w4[c]);

    float4 r;
    r.x = a.x + p * w.x;  r.y = a.y + p * w.y;
    r.z = a.z + p * w.z;  r.w = a.w + p * w.w;

    long long slot = ((long long)u << sn) | rv;           // u*n + rv
    red_add_v4(val + (slot << (s4 + 2)) + (c << 2), r);
}

// ===========================================================================
// Tier 3: fully generic fallbacks.
// ===========================================================================
__global__ void k_init_fused_s(float* __restrict__ out, const float* __restrict__ pad,
                               long long P, int n, int D)
{
    long long totalI = P;
    long long tot = P + P * (long long)D;
    float* val = out + 2 * P;
    long long stride = (long long)gridDim.x * blockDim.x;
    for (long long t = (long long)blockIdx.x * blockDim.x + threadIdx.x;
         t < tot; t += stride) {
        if (t < totalI) {
            long long nn = (long long)n * n;
            int b   = (int)(t / nn);
            int rem = (int)(t - (long long)b * nn);
            int i   = rem / n;
            int j   = rem - i * n;
            out[t]     = (float)(b * n + i);
            out[P + t] = (float)(b * n + j);
        } else {
            long long v = t - totalI;
            val[v] = __ldg(&pad[(int)(v % D)]);
        }
    }
}

__global__ void k_scatter_s(const int* __restrict__ ei, const float* __restrict__ pestat,
                            const float* __restrict__ ea, const float* __restrict__ w,
                            float* __restrict__ val, int E, int K, int D, int n)
{
    long long tot = (long long)E * D;
    long long stride = (long long)gridDim.x * blockDim.x;
    for (long long t = (long long)blockIdx.x * blockDim.x + threadIdx.x;
         t < tot; t += stride) {
        int e = (int)(t / D);
        int d = (int)(t - (long long)e * D);
        int u = __ldg(&ei[e]);
        int v = __ldg(&ei[E + e]);
        int g  = u / n;
        int ru = u - g * n;
        int rv = v % n;
        float p = __ldg(&pestat[(long long)e * K]);
        float x = ea[(long long)e * D + d] + p * __ldg(&w[d]);
        long long base = (((long long)g * n + ru) * n + rv) * (long long)D + d;
        atomicAdd(val + base, x);
    }
}

// ===========================================================================

static inline bool is_pow2(int x) { return x > 0 && (x & (x - 1)) == 0; }
static inline int  ilog2(int x)   { int s = 0; while ((1 << s) < x) s++; return s; }
static inline int grid_for(long long work, int tb)
{
    long long g = (work + tb - 1) / tb;
    if (g > 1048576) g = 1048576;
    if (g < 1) g = 1;
    return (int)g;
}

extern "C" void kernel_launch(void* const* d_in, const int* in_sizes, int n_in,
                              void* d_out, int out_size)
{
    // metadata order: edge_index, pestat, edge_attr, batch, fc_w, padding
    const int*   ei     = (const int*)  d_in[0];
    const float* pestat = (const float*)d_in[1];
    const float* ea     = (const float*)d_in[2];
    const float* fc_w   = (const float*)d_in[4];
    const float* pad    = (const float*)d_in[5];

    const int E = in_sizes[0] / 2;
    const int K = in_sizes[1] / E;
    const int D = in_sizes[2] / E;
    const int N = in_sizes[3];                            // B*n (= rows R)
    const long long P = (long long)out_size / (D + 2);    // B*n*n
    const int n = (int)(P / N);

    float* out = (float*)d_out;
    float* val = out + 2 * P;
    const int D4 = D / 4;

    const bool pow2ok = (D % 4 == 0) && (n % 4 == 0) &&
                        is_pow2(n) && is_pow2(D4) && D4 <= 256 &&
                        ((long long)E * D4 < (1LL << 31));

    const int B = (n > 0) ? N / n : 0;
    const size_t smemB = (size_t)n * D * 4 + (size_t)CHUNK * 4 + 16;
    const bool fusedok = pow2ok && B > 0 && (N % n == 0) && (E % B == 0) &&
                         smemB <= 48 * 1024;

    if (fusedok) {
        const int sn = ilog2(n);
        const int s4 = ilog2(D4);
        const int epg = E / B;
        const int R = N;                                  // dense rows
        const int idxBlocks = (int)(((P >> 2) + TB - 1) / TB);
        k_fused<<<R + idxBlocks, TB, smemB>>>(out, ei, pestat,
                                              (const float4*)ea,
                                              (const float4*)fc_w,
                                              (const float4*)pad,
                                              E, K, s4, sn, epg, P, R);
    } else if (pow2ok) {
        const int sn = ilog2(n);
        const int s4 = ilog2(D4);
        long long P4 = P >> 2;
        long long V4 = P * (long long)D4;
        int idxBlocks = (int)((P4 + TB - 1) / TB);
        int valBlocks = (int)((V4 + TB - 1) / TB);
        k_init_p2<<<idxBlocks + valBlocks, TB>>>(out, (const float4*)pad,
                                                 sn, P, D4, idxBlocks);
        int tot = E << s4;
        k_scatter_p2<<<(tot + TB - 1) / TB, TB>>>(ei, pestat,
                                                  (const float4*)ea,
                                                  (const float4*)fc_w,
                                                  val, E, K, s4, sn);
    } else {
        long long tot = P + P * (long long)D;
        k_init_fused_s<<<grid_for(tot, TB), TB>>>(out, pad, P, n, D);
        long long st = (long long)E * D;
        k_scatter_s<<<grid_for(st, TB), TB>>>(ei, pestat, ea, fc_w, val,
                                              E, K, D, n);
    }
}

// round 6
// speedup vs baseline: 1.2667x; 1.2667x over previous
#include <cuda_runtime.h>
#include <cuda_bf16.h>
#include <stdint.h>

// ---------------------------------------------------------------------------
// Hodge1LapEdgeEncoder
//
// Output (float32): [0,P) idx rows | [P,2P) idx cols | [2P,2P+P*D) dense vals
//   dense[u, rv, :] = padding + sum_{e: ei[0,e]==u, ei[1,e]%n==rv}
//                               (edge_attr[e] + pestat[e,0] * fc_w)
//   (u = g*n+ru is already the dense row id; rows are independent)
//
// Tier 1: bin edges by destination row (counting sort), then one block per
//         row builds the row in smem and streams it out once. No global
//         atomics, dense region written exactly once.
// Tier 2: init + global red.v4 scatter (R4 path).
// Tier 3: fully generic scalar path.
// ---------------------------------------------------------------------------

#define TB 256
#define CAP 128                       // max binned edges per row (fast path)
#define CNT_MAX 65536                 // max rows supported by scratch
#define BIN_MAX (CNT_MAX * CAP)       // 8M ints = 32 MB scratch

__device__ int g_cnt[CNT_MAX];        // zero-init .bss; row kernel re-zeros
__device__ int g_bin[BIN_MAX];

// ===========================================================================
// Tier 1 kernel A: edge binning + idx pattern (fused, block-partitioned).
// ===========================================================================
__global__ void k_bin_idx(const int* __restrict__ ei, int E,
                          float* __restrict__ out, long long P,
                          int sn, int binBlocks)
{
    const int tid = threadIdx.x;
    if ((int)blockIdx.x < binBlocks) {
        int e = blockIdx.x * TB + tid;
        if (e >= E) return;
        int u = __ldg(&ei[e]);
        int pos = atomicAdd(&g_cnt[u], 1);
        if (pos < CAP) g_bin[u * CAP + pos] = e;
        return;
    }
    // idx pattern, float4-vectorized (n % 4 == 0 guaranteed by host guard)
    long long P4 = P >> 2;
    long long t = (long long)((int)blockIdx.x - binBlocks) * TB + tid;
    if (t >= P4) return;
    long long q = t << 2;
    int nm1  = (1 << sn) - 1;
    long long nnm1 = ((long long)1 << (2 * sn)) - 1;
    int b   = (int)(q >> (2 * sn));
    int rem = (int)(q & nnm1);
    int i   = rem >> sn;
    int j   = rem & nm1;
    float rv = (float)((b << sn) + i);
    float cv = (float)((b << sn) + j);
    ((float4*)out)[t]       = make_float4(rv, rv, rv, rv);
    ((float4*)(out + P))[t] = make_float4(cv, cv + 1.f, cv + 2.f, cv + 3.f);
}

// ===========================================================================
// Tier 1 kernel B: one block per dense row. Build row in smem, stream out.
// ===========================================================================
__global__ void k_rows(float* __restrict__ val,          // dense [R, n*D]
                       const int*    __restrict__ ei,    // [2, E]
                       const float*  __restrict__ pestat,// [E, K]
                       const float4* __restrict__ ea4,   // [E, D4]
                       const float4* __restrict__ w4,    // [D4]
                       const float4* __restrict__ pad4,  // [D4]
                       int E, int K, int s4, int sn)
{
    extern __shared__ float smem[];
    float4* acc4 = (float4*)smem;

    const int tid = threadIdx.x;
    const int r   = blockIdx.x;
    const int D4  = 1 << s4;
    const int nD4 = 1 << (sn + s4);          // float4s per row
    const int nm1 = (1 << sn) - 1;

    // Phase A: init accumulator with broadcast padding row.
    for (int s = tid; s < nD4; s += TB)
        acc4[s] = __ldg(&pad4[s & (D4 - 1)]);

    const int m = g_cnt[r];
    __syncthreads();

    if (m <= CAP) {
        // Fast path: binned edge list.
        for (int w = tid; w < (m << s4); w += TB) {
            int li = w >> s4;
            int c  = w & (D4 - 1);
            int e  = g_bin[r * CAP + li];
            int rv = __ldg(&ei[E + e]) & nm1;
            float  p  = __ldg(&pestat[(long long)e * K]);
            float4 a  = __ldg(&ea4[((long long)e << s4) + c]);
            float4 wv = __ldg(&w4[c]);
            float* dst = smem + (((rv << s4) + c) << 2);
            atomicAdd(dst + 0, a.x + p * wv.x);
            atomicAdd(dst + 1, a.y + p * wv.y);
            atomicAdd(dst + 2, a.z + p * wv.z);
            atomicAdd(dst + 3, a.w + p * wv.w);
        }
    } else {
        // Overflow path (never taken for sane inputs): scan all edges.
        for (int e = tid; e < E; e += TB) {
            if (__ldg(&ei[e]) != r) continue;
            int rv = __ldg(&ei[E + e]) & nm1;
            float p = __ldg(&pestat[(long long)e * K]);
            for (int c = 0; c < D4; c++) {
                float4 a  = __ldg(&ea4[((long long)e << s4) + c]);
                float4 wv = __ldg(&w4[c]);
                float* dst = smem + (((rv << s4) + c) << 2);
                atomicAdd(dst + 0, a.x + p * wv.x);
                atomicAdd(dst + 1, a.y + p * wv.y);
                atomicAdd(dst + 2, a.z + p * wv.z);
                atomicAdd(dst + 3, a.w + p * wv.w);
            }
        }
    }
    __syncthreads();

    // Phase C: stream the finished row out (coalesced STG.128).
    float4* orow = ((float4*)val) + (long long)r * nD4;
    for (int s = tid; s < nD4; s += TB)
        orow[s] = acc4[s];

    // Phase D: reset this row's counter for the next graph replay.
    if (tid == 0) g_cnt[r] = 0;
}

// ===========================================================================
// Tier 2: R4 pow2 two-kernel path (init + global vector atomics).
// ===========================================================================
__device__ __forceinline__ void red_add_v4(float* dst, float4 r)
{
#if __CUDA_ARCH__ >= 900
    asm volatile("red.global.add.v4.f32 [%0], {%1, %2, %3, %4};"
                 :: "l"(dst), "f"(r.x), "f"(r.y), "f"(r.z), "f"(r.w)
                 : "memory");
#else
    atomicAdd(dst + 0, r.x); atomicAdd(dst + 1, r.y);
    atomicAdd(dst + 2, r.z); atomicAdd(dst + 3, r.w);
#endif
}

__global__ void k_init_p2(float* __restrict__ out, const float4* __restrict__ pad4,
                          int sn, long long P, int D4, int idxBlocks)
{
    if ((int)blockIdx.x < idxBlocks) {
        long long P4 = P >> 2;
        long long t = (long long)blockIdx.x * blockDim.x + threadIdx.x;
        if (t >= P4) return;
        long long q = t << 2;
        int nm1  = (1 << sn) - 1;
        long long nnm1 = ((long long)1 << (2 * sn)) - 1;
        int b   = (int)(q >> (2 * sn));
        int rem = (int)(q & nnm1);
        int i   = rem >> sn;
        int j   = rem & nm1;
        float rv = (float)((b << sn) + i);
        float cv = (float)((b << sn) + j);
        ((float4*)out)[t]       = make_float4(rv, rv, rv, rv);
        ((float4*)(out + P))[t] = make_float4(cv, cv + 1.f, cv + 2.f, cv + 3.f);
    } else {
        long long v = (long long)((int)blockIdx.x - idxBlocks) * blockDim.x
                      + threadIdx.x;
        long long V4 = P * (long long)D4;
        if (v >= V4) return;
        int c = (int)threadIdx.x & (D4 - 1);
        ((float4*)(out + 2 * P))[v] = __ldg(&pad4[c]);
    }
}

__global__ void k_scatter_p2(const int* __restrict__ ei, const float* __restrict__ pestat,
                             const float4* __restrict__ ea4, const float4* __restrict__ w4,
                             float* __restrict__ val, int E, int K, int s4, int sn)
{
    int tot = E << s4;
    int t = blockIdx.x * blockDim.x + threadIdx.x;
    if (t >= tot) return;
    int e = t >> s4;
    int c = t & ((1 << s4) - 1);
    int nm1 = (1 << sn) - 1;

    int u = __ldg(&ei[e]);
    int v = __ldg(&ei[E + e]);
    int rv = v & nm1;

    float  p = __ldg(&pestat[(long long)e * K]);
    float4 a = __ldg(&ea4[((long long)e << s4) + c]);
    float4 w = __ldg(&w4[c]);

    float4 rr;
    rr.x = a.x + p * w.x;  rr.y = a.y + p * w.y;
    rr.z = a.z + p * w.z;  rr.w = a.w + p * w.w;

    long long slot = ((long long)u << sn) | rv;
    red_add_v4(val + (slot << (s4 + 2)) + (c << 2), rr);
}

// ===========================================================================
// Tier 3: fully generic fallbacks.
// ===========================================================================
__global__ void k_init_fused_s(float* __restrict__ out, const float* __restrict__ pad,
                               long long P, int n, int D)
{
    long long totalI = P;
    long long tot = P + P * (long long)D;
    float* val = out + 2 * P;
    long long stride = (long long)gridDim.x * blockDim.x;
    for (long long t = (long long)blockIdx.x * blockDim.x + threadIdx.x;
         t < tot; t += stride) {
        if (t < totalI) {
            long long nn = (long long)n * n;
            int b   = (int)(t / nn);
            int rem = (int)(t - (long long)b * nn);
            int i   = rem / n;
            int j   = rem - i * n;
            out[t]     = (float)(b * n + i);
            out[P + t] = (float)(b * n + j);
        } else {
            long long v = t - totalI;
            val[v] = __ldg(&pad[(int)(v % D)]);
        }
    }
}

__global__ void k_scatter_s(const int* __restrict__ ei, const float* __restrict__ pestat,
                            const float* __restrict__ ea, const float* __restrict__ w,
                            float* __restrict__ val, int E, int K, int D, int n)
{
    long long tot = (long long)E * D;
    long long stride = (long long)gridDim.x * blockDim.x;
    for (long long t = (long long)blockIdx.x * blockDim.x + threadIdx.x;
         t < tot; t += stride) {
        int e = (int)(t / D);
        int d = (int)(t - (long long)e * D);
        int u = __ldg(&ei[e]);
        int v = __ldg(&ei[E + e]);
        int g  = u / n;
        int ru = u - g * n;
        int rv = v % n;
        float p = __ldg(&pestat[(long long)e * K]);
        float x = ea[(long long)e * D + d] + p * __ldg(&w[d]);
        long long base = (((long long)g * n + ru) * n + rv) * (long long)D + d;
        atomicAdd(val + base, x);
    }
}

// ===========================================================================

static inline bool is_pow2(int x) { return x > 0 && (x & (x - 1)) == 0; }
static inline int  ilog2(int x)   { int s = 0; while ((1 << s) < x) s++; return s; }
static inline int grid_for(long long work, int tb)
{
    long long g = (work + tb - 1) / tb;
    if (g > 1048576) g = 1048576;
    if (g < 1) g = 1;
    return (int)g;
}

extern "C" void kernel_launch(void* const* d_in, const int* in_sizes, int n_in,
                              void* d_out, int out_size)
{
    // metadata order: edge_index, pestat, edge_attr, batch, fc_w, padding
    const int*   ei     = (const int*)  d_in[0];
    const float* pestat = (const float*)d_in[1];
    const float* ea     = (const float*)d_in[2];
    const float* fc_w   = (const float*)d_in[4];
    const float* pad    = (const float*)d_in[5];

    const int E = in_sizes[0] / 2;
    const int K = in_sizes[1] / E;
    const int D = in_sizes[2] / E;
    const int N = in_sizes[3];                            // dense rows R = B*n
    const long long P = (long long)out_size / (D + 2);    // B*n*n
    const int n = (int)(P / N);

    float* out = (float*)d_out;
    float* val = out + 2 * P;
    const int D4 = D / 4;

    const bool pow2ok = (D % 4 == 0) && (n % 4 == 0) &&
                        is_pow2(n) && is_pow2(D4) && D4 <= 256 &&
                        ((long long)E * D4 < (1LL << 31));

    const size_t smemB = (size_t)n * D * 4;
    const bool fusedok = pow2ok && N <= CNT_MAX && smemB <= 48 * 1024 &&
                         (long long)P == (long long)N * n;

    if (fusedok) {
        const int sn = ilog2(n);
        const int s4 = ilog2(D4);
        const int binBlocks = (E + TB - 1) / TB;
        const int idxBlocks = (int)(((P >> 2) + TB - 1) / TB);

        k_bin_idx<<<binBlocks + idxBlocks, TB>>>(ei, E, out, P, sn, binBlocks);
        k_rows<<<N, TB, smemB>>>(val, ei, pestat,
                                 (const float4*)ea, (const float4*)fc_w,
                                 (const float4*)pad, E, K, s4, sn);
    } else if (pow2ok) {
        const int sn = ilog2(n);
        const int s4 = ilog2(D4);
        long long P4 = P >> 2;
        long long V4 = P * (long long)D4;
        int idxBlocks = (int)((P4 + TB - 1) / TB);
        int valBlocks = (int)((V4 + TB - 1) / TB);
        k_init_p2<<<idxBlocks + valBlocks, TB>>>(out, (const float4*)pad,
                                                 sn, P, D4, idxBlocks);
        int tot = E << s4;
        k_scatter_p2<<<(tot + TB - 1) / TB, TB>>>(ei, pestat,
                                                  (const float4*)ea,
                                                  (const float4*)fc_w,
                                                  val, E, K, s4, sn);
    } else {
        long long tot = P + P * (long long)D;
        k_init_fused_s<<<grid_for(tot, TB), TB>>>(out, pad, P, n, D);
        long long st = (long long)E * D;
        k_scatter_s<<<grid_for(st, TB), TB>>>(ei, pestat, ea, fc_w, val,
                                              E, K, D, n);
    }
}